// round 15
// baseline (speedup 1.0000x reference)
#include <cuda_runtime.h>

#define B_   256
#define N_   64
#define K_   12
#define D_   128
#define ROWS 16384

#define F_GRID    148
#define F_RPB     111           // rows per block (148*111 = 16428 >= 16384)
#define F_ITERS   7             // 7*16 = 112 >= 111 row slots per block
#define F_THREADS 512
// floats: Wv 16384 + As 112*128 + uq 128 + uk 128 + c 4
#define F_SM_FLOATS (16384 + 112 * 128 + 128 + 128 + 4)

__device__ __forceinline__ float dot4(float4 a, float4 b) {
    return fmaf(a.x, b.x, fmaf(a.y, b.y, fmaf(a.z, b.z, a.w * b.w)));
}
__device__ __forceinline__ void ffma2(unsigned long long& d, unsigned long long a, unsigned long long b) {
    asm("fma.rn.f32x2 %0, %1, %2, %0;" : "+l"(d) : "l"(a), "l"(b));
}
__device__ __forceinline__ unsigned long long pack2(float x) {
    unsigned long long r;
    asm("mov.b64 %0, {%1, %1};" : "=l"(r) : "f"(x));
    return r;
}
__device__ __forceinline__ float2 unpack2(unsigned long long v) {
    float2 f;
    asm("mov.b64 {%0, %1}, %2;" : "=f"(f.x), "=f"(f.y) : "l"(v));
    return f;
}

__global__ __launch_bounds__(F_THREADS, 1)
void gat_fused(const float* __restrict__ nodes, const float* __restrict__ nbrs,
               const float* __restrict__ mask,
               const float* __restrict__ Wq, const float* __restrict__ bq,
               const float* __restrict__ Wk, const float* __restrict__ bk,
               const float* __restrict__ Wv, const float* __restrict__ bv,
               const float* __restrict__ waq, const float* __restrict__ wak,
               const float* __restrict__ ba,
               float* __restrict__ out)
{
    extern __shared__ float sm[];
    float* wv_s = sm;                     // [128][128]
    float* as_s = sm + 16384;             // [112][128]
    float* uq_s = as_s + 112 * 128;       // [128]
    float* uk_s = uq_s + 128;             // [128]
    float* c_s  = uk_s + 128;             // [1]

    const int tid   = threadIdx.x;
    const int lane  = tid & 31;
    const int wm    = tid >> 5;           // 0..15
    const int start = blockIdx.x * F_RPB;
    const int nrows = min(F_RPB, ROWS - start);

    // ---- Wv -> shared (issued first; drains by the syncthreads) ----
    {
        const float4* src = (const float4*)Wv;
        float4* dst = (float4*)wv_s;
#pragma unroll
        for (int i = tid; i < 16384 / 4; i += F_THREADS) dst[i] = src[i];
    }

    // ---- redundant per-block prologue: uq = Wq@waq, uk = Wk@wak, c ----
    {
        float4 waq4 = __ldg((const float4*)waq + lane);
        float4 wak4 = __ldg((const float4*)wak + lane);
#pragma unroll
        for (int i = 0; i < 8; ++i) {
            const int r = wm * 8 + i;     // 0..127
            float4 a  = __ldg((const float4*)(Wq + r * D_) + lane);
            float4 k4 = __ldg((const float4*)(Wk + r * D_) + lane);
            float sq = dot4(a, waq4);
            float sk = dot4(k4, wak4);
#pragma unroll
            for (int off = 16; off; off >>= 1) {
                sq += __shfl_xor_sync(0xFFFFFFFFu, sq, off);
                sk += __shfl_xor_sync(0xFFFFFFFFu, sk, off);
            }
            if (lane == 0) { uq_s[r] = sq; uk_s[r] = sk; }
        }
        if (wm == 0) {
            float4 xq = __ldg((const float4*)bq + lane);
            float4 xk = __ldg((const float4*)bk + lane);
            float p = dot4(xq, waq4) + dot4(xk, wak4);
#pragma unroll
            for (int off = 16; off; off >>= 1)
                p += __shfl_xor_sync(0xFFFFFFFFu, p, off);
            if (lane == 0) c_s[0] = p + __ldg(ba);
        }
    }
    __syncthreads();   // Wv + uq/uk/c ready

    const float4 uq4 = ((const float4*)uq_s)[lane];
    const float4 uk4 = ((const float4*)uk_s)[lane];
    const float  cc  = c_s[0];
    const float4 bv4 = __ldg((const float4*)(bv + lane * 4));

    float prev_asum = 0.f;

    // ========== pipelined loop: load(i) -> GEMM(i-1) -> attn-math(i) ======
#pragma unroll 1
    for (int i = 0; i < F_ITERS; ++i) {
        const int  rl    = i * 16 + wm;   // this warp's row slot
        const bool valid = rl < nrows;
        const int  row   = start + rl;

        // ---- issue row i's loads into registers (13 LDG.128 + mask) ----
        float4 v[K_ + 1];
        float  m[K_];
        if (valid) {
            v[0] = __ldg((const float4*)(nodes + (size_t)row * D_) + lane);
            const float4* np = (const float4*)(nbrs + (size_t)row * (K_ * D_));
#pragma unroll
            for (int j = 0; j < K_; ++j) v[j + 1] = __ldg(np + j * 32 + lane);
            const float* mp = mask + (size_t)row * K_;
#pragma unroll
            for (int j = 0; j < K_; ++j) m[j] = __ldg(mp + j);
        }

        // ---- GEMM for the previous row while the loads are in flight ----
        __syncwarp();                     // as_s row (i-1) stores visible
        if (i > 0) {
            const int prl = (i - 1) * 16 + wm;
            if (prl < nrows) {
                const float* arow = as_s + prl * 128;
                const float* bb   = wv_s + lane * 4;
                unsigned long long acc0 = 0ull, acc1 = 0ull;
#pragma unroll 2
                for (int k = 0; k < 128; k += 4) {
                    float4 a4 = *(const float4*)(arow + k);
#pragma unroll
                    for (int kk = 0; kk < 4; ++kk) {
                        ulonglong2 b = *(const ulonglong2*)(bb + (k + kk) * 128);
                        float av = (kk == 0) ? a4.x : (kk == 1) ? a4.y
                                 : (kk == 2) ? a4.z : a4.w;
                        unsigned long long ap = pack2(av);
                        ffma2(acc0, ap, b.x);
                        ffma2(acc1, ap, b.y);
                    }
                }
                float2 p0 = unpack2(acc0);
                float2 p1 = unpack2(acc1);
                float4 o = make_float4(fmaf(prev_asum, bv4.x, p0.x),
                                       fmaf(prev_asum, bv4.y, p0.y),
                                       fmaf(prev_asum, bv4.z, p1.x),
                                       fmaf(prev_asum, bv4.w, p1.y));
                *(float4*)(out + (size_t)(start + prl) * D_ + lane * 4) = o;
            }
        }

        // ---- consume row i's registers: dots, reduce, softmax, combine ----
        if (valid) {
            float kd[K_ + 1];
            const float qd = dot4(v[0], uq4);
#pragma unroll
            for (int j = 0; j <= K_; ++j) kd[j] = dot4(v[j], uk4) + qd;

#pragma unroll
            for (int off = 16; off; off >>= 1) {
#pragma unroll
                for (int j = 0; j <= K_; ++j)
                    kd[j] += __shfl_xor_sync(0xFFFFFFFFu, kd[j], off);
            }

            float s = 0.f;
#pragma unroll
            for (int j = 0; j <= K_; ++j) {
                float t = kd[j] + cc;
                t = (t >= 0.f) ? t : 0.2f * t;
                float ej = __expf(t);
                if (j) ej *= m[j - 1];
                kd[j] = ej;
                s += ej;
            }
            const float inv = 1.f / (s + 1e-16f);

            float4 w = make_float4(0.f, 0.f, 0.f, 0.f);
#pragma unroll
            for (int j = 0; j <= K_; ++j) {
                const float a = kd[j] * inv;
                w.x = fmaf(a, v[j].x, w.x);
                w.y = fmaf(a, v[j].y, w.y);
                w.z = fmaf(a, v[j].z, w.z);
                w.w = fmaf(a, v[j].w, w.w);
            }

            ((float4*)(as_s + rl * 128))[lane] = w;
            prev_asum = s * inv;
        }
    }

    // ---- drain: GEMM for the last row slot ----
    __syncwarp();
    {
        const int prl = (F_ITERS - 1) * 16 + wm;
        if (prl < nrows) {
            const float* arow = as_s + prl * 128;
            const float* bb   = wv_s + lane * 4;
            unsigned long long acc0 = 0ull, acc1 = 0ull;
#pragma unroll 2
            for (int k = 0; k < 128; k += 4) {
                float4 a4 = *(const float4*)(arow + k);
#pragma unroll
                for (int kk = 0; kk < 4; ++kk) {
                    ulonglong2 b = *(const ulonglong2*)(bb + (k + kk) * 128);
                    float av = (kk == 0) ? a4.x : (kk == 1) ? a4.y
                             : (kk == 2) ? a4.z : a4.w;
                    unsigned long long ap = pack2(av);
                    ffma2(acc0, ap, b.x);
                    ffma2(acc1, ap, b.y);
                }
            }
            float2 p0 = unpack2(acc0);
            float2 p1 = unpack2(acc1);
            float4 o = make_float4(fmaf(prev_asum, bv4.x, p0.x),
                                   fmaf(prev_asum, bv4.y, p0.y),
                                   fmaf(prev_asum, bv4.z, p1.x),
                                   fmaf(prev_asum, bv4.w, p1.y));
            *(float4*)(out + (size_t)(start + prl) * D_ + lane * 4) = o;
        }
    }
}

extern "C" void kernel_launch(void* const* d_in, const int* in_sizes, int n_in,
                              void* d_out, int out_size) {
    const float* nodes = (const float*)d_in[0];
    const float* nbrs  = (const float*)d_in[1];
    const float* mask  = (const float*)d_in[2];
    const float* Wq    = (const float*)d_in[3];
    const float* bq    = (const float*)d_in[4];
    const float* Wk    = (const float*)d_in[5];
    const float* bk    = (const float*)d_in[6];
    const float* Wv    = (const float*)d_in[7];
    const float* bv    = (const float*)d_in[8];
    const float* waq   = (const float*)d_in[9];
    const float* wak   = (const float*)d_in[10];
    const float* ba    = (const float*)d_in[11];
    float* out = (float*)d_out;

    cudaFuncSetAttribute(gat_fused, cudaFuncAttributeMaxDynamicSharedMemorySize,
                         F_SM_FLOATS * 4);

    gat_fused<<<F_GRID, F_THREADS, F_SM_FLOATS * 4>>>(
        nodes, nbrs, mask, Wq, bq, Wk, bk, Wv, bv, waq, wak, ba, out);
}

// round 17
// speedup vs baseline: 1.5284x; 1.5284x over previous
#include <cuda_runtime.h>

#define B_   256
#define N_   64
#define K_   12
#define D_   128
#define ROWS 16384

#define F_GRID    148
#define F_RPB     111           // rows per block (148*111 = 16428 >= 16384)
#define F_ITERS   7             // 7*16 = 112 >= 111 row slots per block
#define F_THREADS 512
// floats: Wv 16384 + As 112*128 + uq 128 + uk 128 + ssum 112 + c 4
#define F_SM_FLOATS (16384 + 112 * 128 + 128 + 128 + 112 + 4)

__device__ __forceinline__ float dot4(float4 a, float4 b) {
    return fmaf(a.x, b.x, fmaf(a.y, b.y, fmaf(a.z, b.z, a.w * b.w)));
}
__device__ __forceinline__ void ffma2(unsigned long long& d, unsigned long long a, unsigned long long b) {
    asm("fma.rn.f32x2 %0, %1, %2, %0;" : "+l"(d) : "l"(a), "l"(b));
}
__device__ __forceinline__ unsigned long long pack2(float x) {
    unsigned long long r;
    asm("mov.b64 %0, {%1, %1};" : "=l"(r) : "f"(x));
    return r;
}
__device__ __forceinline__ float2 unpack2(unsigned long long v) {
    float2 f;
    asm("mov.b64 {%0, %1}, %2;" : "=f"(f.x), "=f"(f.y) : "l"(v));
    return f;
}

__global__ __launch_bounds__(F_THREADS, 1)
void gat_fused(const float* __restrict__ nodes, const float* __restrict__ nbrs,
               const float* __restrict__ mask,
               const float* __restrict__ Wq, const float* __restrict__ bq,
               const float* __restrict__ Wk, const float* __restrict__ bk,
               const float* __restrict__ Wv, const float* __restrict__ bv,
               const float* __restrict__ waq, const float* __restrict__ wak,
               const float* __restrict__ ba,
               float* __restrict__ out)
{
    extern __shared__ float sm[];
    float* wv_s   = sm;                     // [128][128]
    float* as_s   = sm + 16384;             // [112][128]
    float* uq_s   = as_s + 112 * 128;       // [128]
    float* uk_s   = uq_s + 128;             // [128]
    float* ssum_s = uk_s + 128;             // [112]
    float* c_s    = ssum_s + 112;           // [1]

    const int tid   = threadIdx.x;
    const int lane  = tid & 31;
    const int wm    = tid >> 5;             // 0..15
    const int start = blockIdx.x * F_RPB;
    const int nrows = min(F_RPB, ROWS - start);

    // ---- Wv -> shared (issued first; drains by the syncthreads) ----
    {
        const float4* src = (const float4*)Wv;
        float4* dst = (float4*)wv_s;
#pragma unroll
        for (int i = tid; i < 16384 / 4; i += F_THREADS) dst[i] = src[i];
    }

    // ---- redundant per-block prologue: uq = Wq@waq, uk = Wk@wak, c ----
    {
        float4 waq4 = __ldg((const float4*)waq + lane);
        float4 wak4 = __ldg((const float4*)wak + lane);
#pragma unroll
        for (int i = 0; i < 8; ++i) {
            const int r = wm * 8 + i;       // 0..127
            float4 a  = __ldg((const float4*)(Wq + r * D_) + lane);
            float4 k4 = __ldg((const float4*)(Wk + r * D_) + lane);
            float sq = dot4(a, waq4);
            float sk = dot4(k4, wak4);
#pragma unroll
            for (int off = 16; off; off >>= 1) {
                sq += __shfl_xor_sync(0xFFFFFFFFu, sq, off);
                sk += __shfl_xor_sync(0xFFFFFFFFu, sk, off);
            }
            if (lane == 0) { uq_s[r] = sq; uk_s[r] = sk; }
        }
        if (wm == 0) {
            float4 xq = __ldg((const float4*)bq + lane);
            float4 xk = __ldg((const float4*)bk + lane);
            float p = dot4(xq, waq4) + dot4(xk, wak4);
#pragma unroll
            for (int off = 16; off; off >>= 1)
                p += __shfl_xor_sync(0xFFFFFFFFu, p, off);
            if (lane == 0) c_s[0] = p + __ldg(ba);
        }
    }
    __syncthreads();   // Wv + uq/uk/c ready

    const float4 uq4 = ((const float4*)uq_s)[lane];
    const float4 uk4 = ((const float4*)uk_s)[lane];
    const float  cc  = c_s[0];

    // ========== phase 1: one-pass attention; warp owns rows i*16+wm ==========
#pragma unroll 1
    for (int i = 0; i < F_ITERS; ++i) {
        const int rl = i * 16 + wm;         // local row slot 0..111
        if (rl < nrows) {
            const int row = start + rl;

            // mask prefetch (12 uniform loads)
            float m[K_];
            const float* mp = mask + (size_t)row * K_;
#pragma unroll
            for (int j = 0; j < K_; ++j) m[j] = __ldg(mp + j);

            // load node + 12 neighbors ONCE into registers
            float4 v[K_ + 1];
            v[0] = __ldg((const float4*)(nodes + (size_t)row * D_) + lane);
            const float4* np = (const float4*)(nbrs + (size_t)row * (K_ * D_));
#pragma unroll
            for (int j = 0; j < K_; ++j) v[j + 1] = __ldg(np + j * 32 + lane);

            // 13 sim partials (q-term merged per lane)
            float kd[K_ + 1];
            const float qd = dot4(v[0], uq4);
#pragma unroll
            for (int j = 0; j <= K_; ++j) kd[j] = dot4(v[j], uk4) + qd;

            // butterfly reduce 13 values across the warp
#pragma unroll
            for (int off = 16; off; off >>= 1) {
#pragma unroll
                for (int j = 0; j <= K_; ++j)
                    kd[j] += __shfl_xor_sync(0xFFFFFFFFu, kd[j], off);
            }

            // masked LeakyReLU-exp softmax (tree sum)
            float e[K_ + 1];
#pragma unroll
            for (int j = 0; j <= K_; ++j) {
                float t = kd[j] + cc;
                t = (t >= 0.f) ? t : 0.2f * t;
                float ej = __expf(t);
                if (j) ej *= m[j - 1];
                e[j] = ej;
            }
            float s01 = e[0] + e[1],   s23 = e[2] + e[3];
            float s45 = e[4] + e[5],   s67 = e[6] + e[7];
            float s89 = e[8] + e[9],   sab = e[10] + e[11];
            float s0123 = s01 + s23,   s4567 = s45 + s67;
            float s89ab = s89 + sab;
            float s = (s0123 + s4567) + (s89ab + e[12]);
            const float inv = 1.f / (s + 1e-16f);

            // combine directly from registers (no reload)
            float4 w = make_float4(0.f, 0.f, 0.f, 0.f);
#pragma unroll
            for (int j = 0; j <= K_; ++j) {
                const float a = e[j] * inv;
                w.x = fmaf(a, v[j].x, w.x);
                w.y = fmaf(a, v[j].y, w.y);
                w.z = fmaf(a, v[j].z, w.z);
                w.w = fmaf(a, v[j].w, w.w);
            }

            ((float4*)(as_s + rl * 128))[lane] = w;
            if (lane == 0) ssum_s[rl] = s * inv;
        } else {
            // out-of-range slot: zero so the GEMM stays unguarded
            ((float4*)(as_s + rl * 128))[lane] = make_float4(0.f, 0.f, 0.f, 0.f);
            if (lane == 0) ssum_s[rl] = 0.f;
        }
    }

    __syncwarp();      // warp wrote exactly its own row slots

    // ========== phase 2: GEMM 7 row-slots x 128 cols per warp ==========
    const float* b_base = wv_s + lane * 4;

    unsigned long long acc[F_ITERS][2];
#pragma unroll
    for (int i = 0; i < F_ITERS; ++i) { acc[i][0] = 0ull; acc[i][1] = 0ull; }

#pragma unroll 2
    for (int k = 0; k < 128; k += 4) {
        float4 a4[F_ITERS];
#pragma unroll
        for (int i = 0; i < F_ITERS; ++i)
            a4[i] = *(const float4*)(as_s + (i * 16 + wm) * 128 + k);
#pragma unroll
        for (int kk = 0; kk < 4; ++kk) {
            ulonglong2 b = *(const ulonglong2*)(b_base + (k + kk) * 128);
#pragma unroll
            for (int i = 0; i < F_ITERS; ++i) {
                float av = (kk == 0) ? a4[i].x : (kk == 1) ? a4[i].y
                         : (kk == 2) ? a4[i].z : a4[i].w;
                unsigned long long ap = pack2(av);
                ffma2(acc[i][0], ap, b.x);
                ffma2(acc[i][1], ap, b.y);
            }
        }
    }

    // epilogue: + asum * bv, coalesced stores (guard real rows only)
    float4 bv4 = __ldg((const float4*)(bv + lane * 4));
#pragma unroll
    for (int i = 0; i < F_ITERS; ++i) {
        const int rl = i * 16 + wm;
        if (rl < nrows) {
            const float srow = ssum_s[rl];
            float2 p0 = unpack2(acc[i][0]);
            float2 p1 = unpack2(acc[i][1]);
            float4 o = make_float4(fmaf(srow, bv4.x, p0.x),
                                   fmaf(srow, bv4.y, p0.y),
                                   fmaf(srow, bv4.z, p1.x),
                                   fmaf(srow, bv4.w, p1.y));
            *(float4*)(out + (size_t)(start + rl) * D_ + lane * 4) = o;
        }
    }
}

extern "C" void kernel_launch(void* const* d_in, const int* in_sizes, int n_in,
                              void* d_out, int out_size) {
    const float* nodes = (const float*)d_in[0];
    const float* nbrs  = (const float*)d_in[1];
    const float* mask  = (const float*)d_in[2];
    const float* Wq    = (const float*)d_in[3];
    const float* bq    = (const float*)d_in[4];
    const float* Wk    = (const float*)d_in[5];
    const float* bk    = (const float*)d_in[6];
    const float* Wv    = (const float*)d_in[7];
    const float* bv    = (const float*)d_in[8];
    const float* waq   = (const float*)d_in[9];
    const float* wak   = (const float*)d_in[10];
    const float* ba    = (const float*)d_in[11];
    float* out = (float*)d_out;

    cudaFuncSetAttribute(gat_fused, cudaFuncAttributeMaxDynamicSharedMemorySize,
                         F_SM_FLOATS * 4);

    gat_fused<<<F_GRID, F_THREADS, F_SM_FLOATS * 4>>>(
        nodes, nbrs, mask, Wq, bq, Wk, bk, Wv, bv, waq, wak, ba, out);
}